// round 13
// baseline (speedup 1.0000x reference)
#include <cuda_runtime.h>
#include <cuda_fp16.h>
#include <cstdint>

// FeatureTransformer_5909875000395
//   d_in[0]: ft_ics  int32  [16384, 32]   (pad = -1)
//   d_in[1]: weight  fp32   [41024, 257]
//   d_in[2]: bias    fp32   [256]
// Output: fts [16384,256] then psqt [16384,1]  (fp32)
//
// bias_full = [0, bias[0..255]]: fts col 0 no bias, col c gets bias[c-1],
// psqt col gets bias[255].
//
// R13: gather frozen at the L2 wall (R12). Convert rebuilt as a flat float4
// streaming pass: 16B-aligned loads over the raw 10.5M-float array (1x L1
// wavefront efficiency on the 42MB read side), per-element dst remap using
// dst = e - e/257.

#define BATCH      16384
#define MAX_ACTIVE 32
#define N_OUT      256
#define N_IN       41024
#define ROW_W      257

#define TOTAL_ELEMS  (N_IN * ROW_W)            // 10,543,168
#define NCHUNK       (TOTAL_ELEMS / 4)         // 2,635,792 float4 chunks
#define CONV_CTAS    2575                      // 2575*256*4 >= NCHUNK

// +1 zero row at index N_IN for padded slots (device globals zero-init;
// convert_kernel never writes row N_IN, so it stays zero across replays).
__device__ __half g_wh[(size_t)(N_IN + 1) * N_OUT];   // ~21 MB, 512B rows
__device__ float  g_ps[N_IN + 1];                      // psqt col, fp32

// --------------------------------------------------------------- convert ---
// Flat float4 pass. Thread handles 4 chunks strided by grid size (coalesced,
// 4 independent LDG.128 in flight). Element e -> row r = e/257; fts dst
// offset is e - r; col 256 goes to g_ps[r].
__global__ __launch_bounds__(256)
void convert_kernel(const float* __restrict__ w)
{
    const unsigned int T = CONV_CTAS * 256u;
    const unsigned int t = blockIdx.x * 256u + threadIdx.x;

    #pragma unroll
    for (int k = 0; k < 4; ++k) {
        const unsigned int chunk = t + (unsigned int)k * T;
        if (chunk < NCHUNK) {
            const float4 v = __ldg((const float4*)w + chunk);
            const unsigned int e = chunk * 4u;
            const float f[4] = {v.x, v.y, v.z, v.w};
            #pragma unroll
            for (int i = 0; i < 4; ++i) {
                const unsigned int ei = e + i;
                const unsigned int r  = ei / 257u;          // umulhi
                const unsigned int c  = ei - r * 257u;
                if (c == 256u) g_ps[r] = f[i];
                else           g_wh[ei - r] = __float2half_rn(f[i]);
            }
        }
    }
}

// ---------------------------------------------------------------- gather ---
// (frozen at the L2-byte wall — R12)
// CTA = 256 threads = 4 batch rows x 64 threads. Thread owns cols
// {4*lt .. 4*lt+3} via one uint2 (2x half2) load per index. 32 indices in
// 8 groups of 4, each summed with a 2-level fp16 tree then fp32. psqt loads
// issued early so they complete under the main loop.
__global__ __launch_bounds__(256, 6)
void gather_kernel(const int*   __restrict__ ft_ics,
                   const float* __restrict__ bias,
                   float*       __restrict__ out)
{
    __shared__ int sidx[4 * MAX_ACTIVE];

    const int tid  = threadIdx.x;
    const int row0 = blockIdx.x * 4;

    if (tid < 4 * MAX_ACTIVE) {
        int v = ft_ics[row0 * MAX_ACTIVE + tid];
        sidx[tid] = (v < 0) ? N_IN : v;              // branchless in the loop
    }
    __syncthreads();

    const int g    = tid >> 6;          // row group: 0..3
    const int lt   = tid & 63;          // thread within row
    const int row  = row0 + g;
    const int c    = lt << 2;           // first col owned (multiple of 4)
    const int* idxp = &sidx[g * MAX_ACTIVE];

    // psqt load issued early; butterfly-reduced after the main loop.
    const int wid  = tid >> 5;
    const int lane = tid & 31;
    float p = (wid < 4) ? __ldg(g_ps + sidx[wid * MAX_ACTIVE + lane]) : 0.0f;

    // Shifted-bias init: col c gets bias[c-1] (col 0 gets 0).
    float a0 = (c == 0) ? 0.0f : __ldg(bias + c - 1);
    float a1 = __ldg(bias + c);
    float a2 = __ldg(bias + c + 1);
    float a3 = __ldg(bias + c + 2);

    #pragma unroll
    for (int i = 0; i < MAX_ACTIVE; i += 4) {
        const int i0 = idxp[i];
        const int i1 = idxp[i + 1];
        const int i2 = idxp[i + 2];
        const int i3 = idxp[i + 3];
        const uint2 v0 = __ldg((const uint2*)(g_wh + ((size_t)i0 << 8)) + lt);
        const uint2 v1 = __ldg((const uint2*)(g_wh + ((size_t)i1 << 8)) + lt);
        const uint2 v2 = __ldg((const uint2*)(g_wh + ((size_t)i2 << 8)) + lt);
        const uint2 v3 = __ldg((const uint2*)(g_wh + ((size_t)i3 << 8)) + lt);

        // 2-level fp16 tree on each half2 lane pair.
        const __half2 sx = __hadd2(
            __hadd2(*(const __half2*)&v0.x, *(const __half2*)&v1.x),
            __hadd2(*(const __half2*)&v2.x, *(const __half2*)&v3.x));
        const __half2 sy = __hadd2(
            __hadd2(*(const __half2*)&v0.y, *(const __half2*)&v1.y),
            __hadd2(*(const __half2*)&v2.y, *(const __half2*)&v3.y));

        const float2 fx = __half22float2(sx);
        const float2 fy = __half22float2(sy);
        a0 += fx.x; a1 += fx.y; a2 += fy.x; a3 += fy.y;
    }

    *(float4*)(out + (size_t)row * N_OUT + c) = make_float4(a0, a1, a2, a3);

    // psqt: warps 0..3 handle rows 0..3 (g_ps[N_IN] == 0 for pads).
    if (wid < 4) {
        #pragma unroll
        for (int off = 16; off > 0; off >>= 1)
            p += __shfl_xor_sync(0xffffffffu, p, off);
        if (lane == 0)
            out[(size_t)BATCH * N_OUT + row0 + wid] = p + __ldg(bias + 255);
    }
}

// ---------------------------------------------------------------- launch ---
extern "C" void kernel_launch(void* const* d_in, const int* in_sizes, int n_in,
                              void* d_out, int out_size)
{
    const int*   ft_ics = (const int*)  d_in[0];
    const float* weight = (const float*)d_in[1];
    const float* bias   = (const float*)d_in[2];
    float*       out    = (float*)      d_out;

    convert_kernel<<<CONV_CTAS, 256>>>(weight);
    gather_kernel<<<BATCH / 4, 256>>>(ft_ics, bias, out);
}

// round 14
// speedup vs baseline: 1.4294x; 1.4294x over previous
#include <cuda_runtime.h>
#include <cuda_fp16.h>
#include <cstdint>

// FeatureTransformer_5909875000395
//   d_in[0]: ft_ics  int32  [16384, 32]   (pad = -1)
//   d_in[1]: weight  fp32   [41024, 257]
//   d_in[2]: bias    fp32   [256]
// Output: fts [16384,256] then psqt [16384,1]  (fp32)
//
// bias_full = [0, bias[0..255]]: fts col 0 no bias, col c gets bias[c-1],
// psqt col gets bias[255].
//
// R14: full revert to R12 (best: 27.1us). Convert keeps the proven stride-2
// lane-pair pattern but processes 2 rows per warp (8 loads in flight instead
// of 4; identical load/store shapes). Gather frozen at the L2 wall.

#define BATCH      16384
#define MAX_ACTIVE 32
#define N_OUT      256
#define N_IN       41024
#define ROW_W      257

// +1 zero row at index N_IN for padded slots (device globals zero-init;
// convert_kernel never writes row N_IN, so it stays zero across replays).
__device__ __half g_wh[(size_t)(N_IN + 1) * N_OUT];   // ~21 MB, 512B rows
__device__ float  g_ps[N_IN + 1];                      // psqt col, fp32

// --------------------------------------------------------------- convert ---
// One warp per 2 weight rows. Per row: lane handles col pairs {p*64+2*lane},
// packed half2 conversion, 4B stores (exact R10/R12 access pattern — 2 lines
// per scalar LDG, 128B coalesced store wavefronts).
__global__ __launch_bounds__(256)
void convert_kernel(const float* __restrict__ w)
{
    const int wg   = (blockIdx.x << 3) + (threadIdx.x >> 5);   // global warp
    const int lane = threadIdx.x & 31;
    const int r0   = wg << 1;                                   // 2 rows/warp

    #pragma unroll
    for (int r = 0; r < 2; ++r) {
        const float* src = w + (size_t)(r0 + r) * ROW_W;
        __half*      dst = g_wh + ((size_t)(r0 + r) << 8);
        #pragma unroll
        for (int p = 0; p < 4; ++p) {
            const int c = (p << 6) + (lane << 1);
            const float a = __ldg(src + c);
            const float b = __ldg(src + c + 1);
            *(__half2*)(dst + c) = __floats2half2_rn(a, b);
        }
    }
    if (lane < 2)
        g_ps[r0 + lane] = __ldg(w + (size_t)(r0 + lane) * ROW_W + 256);
}

// ---------------------------------------------------------------- gather ---
// (frozen at the L2-byte wall — R12, best 19.7us)
// CTA = 256 threads = 4 batch rows x 64 threads. Thread owns cols
// {4*lt .. 4*lt+3} via one uint2 (2x half2) load per index. 32 indices in
// 8 groups of 4, each summed with a 2-level fp16 tree then fp32. psqt loads
// issued early so they complete under the main loop.
__global__ __launch_bounds__(256, 6)
void gather_kernel(const int*   __restrict__ ft_ics,
                   const float* __restrict__ bias,
                   float*       __restrict__ out)
{
    __shared__ int sidx[4 * MAX_ACTIVE];

    const int tid  = threadIdx.x;
    const int row0 = blockIdx.x * 4;

    if (tid < 4 * MAX_ACTIVE) {
        int v = ft_ics[row0 * MAX_ACTIVE + tid];
        sidx[tid] = (v < 0) ? N_IN : v;              // branchless in the loop
    }
    __syncthreads();

    const int g    = tid >> 6;          // row group: 0..3
    const int lt   = tid & 63;          // thread within row
    const int row  = row0 + g;
    const int c    = lt << 2;           // first col owned (multiple of 4)
    const int* idxp = &sidx[g * MAX_ACTIVE];

    // psqt load issued early; butterfly-reduced after the main loop.
    const int wid  = tid >> 5;
    const int lane = tid & 31;
    float p = (wid < 4) ? __ldg(g_ps + sidx[wid * MAX_ACTIVE + lane]) : 0.0f;

    // Shifted-bias init: col c gets bias[c-1] (col 0 gets 0).
    float a0 = (c == 0) ? 0.0f : __ldg(bias + c - 1);
    float a1 = __ldg(bias + c);
    float a2 = __ldg(bias + c + 1);
    float a3 = __ldg(bias + c + 2);

    #pragma unroll
    for (int i = 0; i < MAX_ACTIVE; i += 4) {
        const int i0 = idxp[i];
        const int i1 = idxp[i + 1];
        const int i2 = idxp[i + 2];
        const int i3 = idxp[i + 3];
        const uint2 v0 = __ldg((const uint2*)(g_wh + ((size_t)i0 << 8)) + lt);
        const uint2 v1 = __ldg((const uint2*)(g_wh + ((size_t)i1 << 8)) + lt);
        const uint2 v2 = __ldg((const uint2*)(g_wh + ((size_t)i2 << 8)) + lt);
        const uint2 v3 = __ldg((const uint2*)(g_wh + ((size_t)i3 << 8)) + lt);

        // 2-level fp16 tree on each half2 lane pair.
        const __half2 sx = __hadd2(
            __hadd2(*(const __half2*)&v0.x, *(const __half2*)&v1.x),
            __hadd2(*(const __half2*)&v2.x, *(const __half2*)&v3.x));
        const __half2 sy = __hadd2(
            __hadd2(*(const __half2*)&v0.y, *(const __half2*)&v1.y),
            __hadd2(*(const __half2*)&v2.y, *(const __half2*)&v3.y));

        const float2 fx = __half22float2(sx);
        const float2 fy = __half22float2(sy);
        a0 += fx.x; a1 += fx.y; a2 += fy.x; a3 += fy.y;
    }

    *(float4*)(out + (size_t)row * N_OUT + c) = make_float4(a0, a1, a2, a3);

    // psqt: warps 0..3 handle rows 0..3 (g_ps[N_IN] == 0 for pads).
    if (wid < 4) {
        #pragma unroll
        for (int off = 16; off > 0; off >>= 1)
            p += __shfl_xor_sync(0xffffffffu, p, off);
        if (lane == 0)
            out[(size_t)BATCH * N_OUT + row0 + wid] = p + __ldg(bias + 255);
    }
}

// ---------------------------------------------------------------- launch ---
extern "C" void kernel_launch(void* const* d_in, const int* in_sizes, int n_in,
                              void* d_out, int out_size)
{
    const int*   ft_ics = (const int*)  d_in[0];
    const float* weight = (const float*)d_in[1];
    const float* bias   = (const float*)d_in[2];
    float*       out    = (float*)      d_out;

    convert_kernel<<<N_IN / 16, 256>>>(weight);
    gather_kernel<<<BATCH / 4, 256>>>(ft_ics, bias, out);
}